// round 4
// baseline (speedup 1.0000x reference)
#include <cuda_runtime.h>
#include <stdint.h>

#define NN 100000
#define EE 1600000
#define DD 32
#define KTOP 1024
#define HBITS 17
#define HSIZE (1 << HBITS)
#define CAP 4096

// ---------------- scratch (device globals; no allocation allowed) ----------------
__device__ int   g_rowcnt[NN];
__device__ int   g_rowptr[NN + 1];
__device__ int   g_cursor[NN];
__device__ int   g_perm[EE];
__device__ int   g_cols_p[EE];
__device__ float g_v0[EE], g_v1[EE], g_v2[EE], g_v3[EE];
__device__ float g_emb_a[NN * DD], g_emb_b[NN * DD], g_emb_sum[NN * DD];
__device__ float g_num_a[NN], g_num_b[NN], g_num_sum[NN];
__device__ float g_order[NN];
__device__ float g_scores[NN];
__device__ int   g_hist[HSIZE];
__device__ int   g_sel_digit;
__device__ int   g_cand_cnt;
__device__ unsigned int g_cand_key[CAP];
__device__ int   g_cand_idx[CAP];

// ---------------- threefry2x32 (JAX-compatible) ----------------
__host__ __device__ __forceinline__ void tf2x32(uint32_t k0, uint32_t k1,
                                                uint32_t x0, uint32_t x1,
                                                uint32_t &o0, uint32_t &o1) {
    uint32_t ks2 = k0 ^ k1 ^ 0x1BD11BDAu;
    x0 += k0; x1 += k1;
#define TFR(r) do { x0 += x1; x1 = (x1 << (r)) | (x1 >> (32 - (r))); x1 ^= x0; } while (0)
    TFR(13); TFR(15); TFR(26); TFR(6);
    x0 += k1;  x1 += ks2 + 1u;
    TFR(17); TFR(29); TFR(16); TFR(24);
    x0 += ks2; x1 += k0 + 2u;
    TFR(13); TFR(15); TFR(26); TFR(6);
    x0 += k0;  x1 += k1 + 3u;
    TFR(17); TFR(29); TFR(16); TFR(24);
    x0 += k1;  x1 += ks2 + 4u;
    TFR(13); TFR(15); TFR(26); TFR(6);
    x0 += ks2; x1 += k0 + 5u;
#undef TFR
    o0 = x0; o1 = x1;
}

// jax_threefry_partitionable=True, bit_width=32: counter i (uint64, hi=0 here),
// bits = out0 ^ out1.
__device__ __forceinline__ uint32_t rbits32(uint32_t k0, uint32_t k1, uint32_t i) {
    uint32_t a, b;
    tf2x32(k0, k1, 0u, i, a, b);
    return a ^ b;
}

__device__ __forceinline__ float u01(uint32_t bits) {
    return __uint_as_float((bits >> 9) | 0x3f800000u) - 1.0f;
}

__device__ __forceinline__ uint32_t score_key(float f) {
    uint32_t b = __float_as_uint(f);
    return (b & 0x80000000u) ? ~b : (b | 0x80000000u);
}

// ---------------- CSR build ----------------
__global__ void zero_kernel() {
    int i = blockIdx.x * blockDim.x + threadIdx.x;
    if (i < HSIZE) g_hist[i] = 0;
    if (i < NN) g_rowcnt[i] = 0;
    if (i == 0) g_cand_cnt = 0;
}

__global__ void rowcnt_kernel(const int* __restrict__ rows) {
    int e = blockIdx.x * blockDim.x + threadIdx.x;
    if (e >= EE) return;
    atomicAdd(&g_rowcnt[rows[e]], 1);
}

__global__ void scan_kernel() {   // 1 block, 1024 threads
    __shared__ int part[1024];
    const int T = 1024;
    const int CH = (NN + T - 1) / T;
    int t = threadIdx.x;
    int s = t * CH;
    int e = s + CH; if (e > NN) e = NN;
    int sum = 0;
    for (int i = s; i < e; i++) sum += g_rowcnt[i];
    part[t] = sum;
    __syncthreads();
    if (t == 0) {
        int run = 0;
        for (int i = 0; i < T; i++) { int v = part[i]; part[i] = run; run += v; }
    }
    __syncthreads();
    int run = part[t];
    for (int i = s; i < e; i++) { g_rowptr[i] = run; run += g_rowcnt[i]; }
    if (t == T - 1) g_rowptr[NN] = run;
}

__global__ void cursor_kernel() {
    int i = blockIdx.x * blockDim.x + threadIdx.x;
    if (i < NN) g_cursor[i] = g_rowptr[i];
}

__global__ void scatter_kernel(const int* __restrict__ rows) {
    int e = blockIdx.x * blockDim.x + threadIdx.x;
    if (e >= EE) return;
    int pos = atomicAdd(&g_cursor[rows[e]], 1);
    g_perm[pos] = e;
}

// Per-row insertion sort of edge ids: makes per-row accumulation order
// deterministic (ascending original edge id) regardless of atomic order.
__global__ void rowsort_kernel() {
    int r = blockIdx.x * blockDim.x + threadIdx.x;
    if (r >= NN) return;
    int s = g_rowptr[r], e = g_rowptr[r + 1];
    for (int i = s + 1; i < e; i++) {
        int v = g_perm[i];
        int j = i - 1;
        while (j >= s && g_perm[j] > v) { g_perm[j + 1] = g_perm[j]; j--; }
        g_perm[j + 1] = v;
    }
}

// ---------------- dropout masks (threefry) + permuted edge data ----------------
__global__ void keep_kernel(const int* __restrict__ cols, const float* __restrict__ adj,
                            uint32_t a0, uint32_t a1, uint32_t b0, uint32_t b1,
                            uint32_t c0, uint32_t c1) {
    int j = blockIdx.x * blockDim.x + threadIdx.x;
    if (j >= EE) return;
    int e = g_perm[j];
    g_cols_p[j] = cols[e];
    float v = adj[e];
    g_v0[j] = v;
    v *= floorf(u01(rbits32(a0, a1, (uint32_t)e)) + 0.5f);
    g_v1[j] = v;
    v *= floorf(u01(rbits32(b0, b1, (uint32_t)e)) + 0.25f);
    g_v2[j] = v;
    v *= floorf(u01(rbits32(c0, c1, (uint32_t)e)) + 0.125f);
    g_v3[j] = v;
}

// ---------------- fused propagation step: warp per row, lane = dim ----------------
__global__ void step_kernel(const float* __restrict__ embeds, int step) {
    int gid = blockIdx.x * blockDim.x + threadIdx.x;
    int r = gid >> 5;
    int lane = threadIdx.x & 31;
    if (r >= NN) return;

    const float* vals = (step == 0) ? g_v0 : (step == 1) ? g_v1 : (step == 2) ? g_v2 : g_v3;
    const float* emb_cur = (step == 0) ? embeds : ((step & 1) ? g_emb_a : g_emb_b);
    float*       emb_next = (step & 1) ? g_emb_b : g_emb_a;
    const float* num_cur = (step & 1) ? g_num_a : g_num_b;
    float*       num_next = (step & 1) ? g_num_b : g_num_a;

    int s = g_rowptr[r], e = g_rowptr[r + 1];
    float acc = 0.f, accn = 0.f, acco = 0.f;
    for (int j = s; j < e; j++) {
        int c = __ldg(&g_cols_p[j]);
        float v = __ldg(&vals[j]);
        acc += v * __ldg(&emb_cur[c * DD + lane]);
        if (step) accn += v * __ldg(&num_cur[c]);
        acco += v;
    }
    float ec = emb_cur[r * DD + lane];
    if (step == 0) {
        float en = acc - ec;
        g_emb_a[r * DD + lane] = en;          // emb_next for step 0
        g_emb_sum[r * DD + lane] = en;
        if (lane == 0) { g_num_a[r] = acco; g_num_sum[r] = acco; g_order[r] = acco; }
    } else {
        float od = g_order[r];
        float en = acc - ec - od * ec;
        emb_next[r * DD + lane] = en;
        g_emb_sum[r * DD + lane] += en;
        if (lane == 0) {
            float nn = accn - num_cur[r] - od;
            num_next[r] = nn;
            g_num_sum[r] += nn;
            g_order[r] = acco;                // order for next iteration (own row: safe)
        }
    }
}

// ---------------- scoring (normalize + dot + Gumbel) ----------------
__global__ void score_kernel(const float* __restrict__ embeds, float* __restrict__ out,
                             int n_score_out) {
    int gid = blockIdx.x * blockDim.x + threadIdx.x;
    int i = gid >> 5;
    int lane = threadIdx.x & 31;
    if (i >= NN) return;

    float ns = g_num_sum[i] + 1e-8f;
    float sub = g_emb_sum[i * DD + lane] / ns;
    float em = embeds[i * DD + lane];
    float ss = sub * sub, ee = em * em;
    for (int o = 16; o; o >>= 1) {
        ss += __shfl_xor_sync(0xffffffffu, ss, o);
        ee += __shfl_xor_sync(0xffffffffu, ee, o);
    }
    float a = sub / fmaxf(sqrtf(ss), 1e-12f);
    float b = em / fmaxf(sqrtf(ee), 1e-12f);
    float d = a * b;
    for (int o = 16; o; o >>= 1) d += __shfl_xor_sync(0xffffffffu, d, o);

    if (lane == 0) {
        float u = u01(rbits32(0u, 7u, (uint32_t)i));   // key(7)
        float sc = d + (-logf(-logf(u)));
        g_scores[i] = sc;
        if (i < n_score_out) out[i] = sc;
    }
}

// ---------------- top-k: histogram threshold + compact + bitonic ----------------
__global__ void hist_kernel() {
    int i = blockIdx.x * blockDim.x + threadIdx.x;
    if (i >= NN) return;
    atomicAdd(&g_hist[score_key(g_scores[i]) >> (32 - HBITS)], 1);
}

__global__ void thresh_kernel() {   // 1 block, 1024 threads
    __shared__ int part[1024];
    const int T = 1024, CH = HSIZE / 1024;   // 128
    int t = threadIdx.x;
    int s = t * CH;
    int sum = 0;
    for (int i = 0; i < CH; i++) sum += g_hist[s + i];
    part[t] = sum;
    __syncthreads();
    if (t == 0) {
        int cum = 0, d = 0;
        for (int tt = T - 1; tt >= 0; tt--) {
            if (cum + part[tt] >= KTOP) {
                for (int b = tt * CH + CH - 1; b >= tt * CH; b--) {
                    int h = g_hist[b];
                    if (cum + h >= KTOP) { d = b; break; }
                    cum += h;
                }
                break;
            }
            cum += part[tt];
        }
        g_sel_digit = d;
    }
}

__global__ void compact_kernel() {
    int i = blockIdx.x * blockDim.x + threadIdx.x;
    if (i >= NN) return;
    uint32_t k = score_key(g_scores[i]);
    if ((int)(k >> (32 - HBITS)) >= g_sel_digit) {
        int p = atomicAdd(&g_cand_cnt, 1);
        if (p < CAP) { g_cand_key[p] = k; g_cand_idx[p] = i; }
    }
}

__global__ void final_kernel(float* __restrict__ out, int out_size) {  // 1 block, 1024 thr
    __shared__ unsigned long long sm[CAP];
    int n = g_cand_cnt; if (n > CAP) n = CAP;
    for (int i = threadIdx.x; i < CAP; i += blockDim.x) {
        // combined: key in high 32 bits, ~idx low -> desc key, asc idx on ties
        sm[i] = (i < n)
            ? ((((unsigned long long)g_cand_key[i]) << 32) | (uint32_t)(~(uint32_t)g_cand_idx[i]))
            : 0ull;
    }
    __syncthreads();
    for (int size = 2; size <= CAP; size <<= 1) {
        for (int stride = size >> 1; stride > 0; stride >>= 1) {
            for (int i = threadIdx.x; i < CAP / 2; i += blockDim.x) {
                int lo = 2 * i - (i & (stride - 1));
                int hi = lo + stride;
                bool desc = ((lo & size) == 0);
                unsigned long long a = sm[lo], b = sm[hi];
                bool sw = desc ? (a < b) : (a > b);
                if (sw) { sm[lo] = b; sm[hi] = a; }
            }
            __syncthreads();
        }
    }
    for (int j = threadIdx.x; j < KTOP; j += blockDim.x) {
        uint32_t idx = ~(uint32_t)(sm[j] & 0xffffffffull);
        if (out_size >= NN + KTOP) out[NN + j] = (float)idx;
        else if (out_size == KTOP) ((int*)out)[j] = (int)idx;
    }
}

// ---------------- launch ----------------
extern "C" void kernel_launch(void* const* d_in, const int* in_sizes, int n_in,
                              void* d_out, int out_size) {
    const int* rows = (const int*)d_in[0];       // edge_index[0]
    const int* cols = rows + EE;                 // edge_index[1]
    const float* adj = (const float*)d_in[1];
    const float* embeds = (const float*)d_in[2];
    float* out = (float*)d_out;
    (void)in_sizes; (void)n_in;

    // fold_in(key(42), i) on host: threefry((0,42), (0,i)) -> new key
    uint32_t fk[3][2];
    for (uint32_t i = 0; i < 3; i++) tf2x32(0u, 42u, 0u, i, fk[i][0], fk[i][1]);

    const int tb = 256;
    zero_kernel<<<(HSIZE + tb - 1) / tb, tb>>>();
    rowcnt_kernel<<<(EE + tb - 1) / tb, tb>>>(rows);
    scan_kernel<<<1, 1024>>>();
    cursor_kernel<<<(NN + tb - 1) / tb, tb>>>();
    scatter_kernel<<<(EE + tb - 1) / tb, tb>>>(rows);
    rowsort_kernel<<<(NN + tb - 1) / tb, tb>>>();
    keep_kernel<<<(EE + tb - 1) / tb, tb>>>(cols, adj,
        fk[0][0], fk[0][1], fk[1][0], fk[1][1], fk[2][0], fk[2][1]);

    for (int s = 0; s < 4; s++)
        step_kernel<<<(NN * 32 + tb - 1) / tb, tb>>>(embeds, s);

    int n_score_out = (out_size == KTOP) ? 0 : ((out_size < NN) ? out_size : NN);
    score_kernel<<<(NN * 32 + tb - 1) / tb, tb>>>(embeds, out, n_score_out);

    hist_kernel<<<(NN + tb - 1) / tb, tb>>>();
    thresh_kernel<<<1, 1024>>>();
    compact_kernel<<<(NN + tb - 1) / tb, tb>>>();
    final_kernel<<<1, 1024>>>(out, out_size);
}

// round 5
// speedup vs baseline: 1.3724x; 1.3724x over previous
#include <cuda_runtime.h>
#include <stdint.h>

#define NN 100000
#define EE 1600000
#define DD 32
#define KTOP 1024
#define HBITS 17
#define HSIZE (1 << HBITS)
#define CAP 4096
#define SCAN_B 98   // ceil(NN / 1024)

// ---------------- scratch (device globals; no allocation allowed) ----------------
__device__ int    g_rowcnt[NN];
__device__ int    g_rowptr[NN + 1];
__device__ int    g_cursor[NN];
__device__ int    g_perm[EE];
__device__ float2 g_cv0[EE], g_cv1[EE], g_cv2[EE], g_cv3[EE];   // (col bits, val)
__device__ float  g_emb_a[NN * DD], g_emb_b[NN * DD], g_emb_sum[NN * DD];
__device__ float  g_num_a[NN], g_num_b[NN], g_num_sum[NN];
__device__ float  g_order[NN];
__device__ float  g_scores[NN];
__device__ int    g_hist[HSIZE];
__device__ int    g_blockTot[SCAN_B], g_blockOff[SCAN_B];
__device__ int    g_sel_digit;
__device__ int    g_cand_cnt;
__device__ unsigned int g_cand_key[CAP];
__device__ int    g_cand_idx[CAP];

// ---------------- threefry2x32 (JAX-compatible, partitionable mode) ----------------
__host__ __device__ __forceinline__ void tf2x32(uint32_t k0, uint32_t k1,
                                                uint32_t x0, uint32_t x1,
                                                uint32_t &o0, uint32_t &o1) {
    uint32_t ks2 = k0 ^ k1 ^ 0x1BD11BDAu;
    x0 += k0; x1 += k1;
#define TFR(r) do { x0 += x1; x1 = (x1 << (r)) | (x1 >> (32 - (r))); x1 ^= x0; } while (0)
    TFR(13); TFR(15); TFR(26); TFR(6);
    x0 += k1;  x1 += ks2 + 1u;
    TFR(17); TFR(29); TFR(16); TFR(24);
    x0 += ks2; x1 += k0 + 2u;
    TFR(13); TFR(15); TFR(26); TFR(6);
    x0 += k0;  x1 += k1 + 3u;
    TFR(17); TFR(29); TFR(16); TFR(24);
    x0 += k1;  x1 += ks2 + 4u;
    TFR(13); TFR(15); TFR(26); TFR(6);
    x0 += ks2; x1 += k0 + 5u;
#undef TFR
    o0 = x0; o1 = x1;
}

__device__ __forceinline__ uint32_t rbits32(uint32_t k0, uint32_t k1, uint32_t i) {
    uint32_t a, b;
    tf2x32(k0, k1, 0u, i, a, b);
    return a ^ b;
}

__device__ __forceinline__ float u01(uint32_t bits) {
    return __uint_as_float((bits >> 9) | 0x3f800000u) - 1.0f;
}

__device__ __forceinline__ uint32_t score_key(float f) {
    uint32_t b = __float_as_uint(f);
    return (b & 0x80000000u) ? ~b : (b | 0x80000000u);
}

// ---------------- init ----------------
__global__ void zero_kernel() {
    int i = blockIdx.x * blockDim.x + threadIdx.x;
    if (i < HSIZE) g_hist[i] = 0;
    if (i < NN) g_rowcnt[i] = 0;
    if (i == 0) g_cand_cnt = 0;
}

__global__ void rowcnt_kernel(const int* __restrict__ rows) {
    int e = blockIdx.x * blockDim.x + threadIdx.x;
    if (e >= EE) return;
    atomicAdd(&g_rowcnt[rows[e]], 1);
}

// ---------------- 3-phase exclusive scan of rowcnt -> rowptr ----------------
__global__ void scan1_kernel() {           // SCAN_B blocks x 1024
    __shared__ int sm[1024];
    int t = threadIdx.x, b = blockIdx.x, i = b * 1024 + t;
    int x = (i < NN) ? g_rowcnt[i] : 0;
    sm[t] = x;
    __syncthreads();
    for (int off = 1; off < 1024; off <<= 1) {
        int y = (t >= off) ? sm[t - off] : 0;
        __syncthreads();
        sm[t] += y;
        __syncthreads();
    }
    if (i < NN) g_rowptr[i] = sm[t] - x;   // local exclusive
    if (t == 1023) g_blockTot[b] = sm[t];
}

__global__ void scan2_kernel() {           // 1 block
    if (threadIdx.x == 0) {
        int run = 0;
        for (int b = 0; b < SCAN_B; b++) { int v = g_blockTot[b]; g_blockOff[b] = run; run += v; }
        g_rowptr[NN] = run;                // == EE
    }
}

__global__ void scan3_kernel() {           // SCAN_B blocks x 1024: add offsets, init cursor
    int t = threadIdx.x, b = blockIdx.x, i = b * 1024 + t;
    if (i < NN) {
        int v = g_rowptr[i] + g_blockOff[b];
        g_rowptr[i] = v;
        g_cursor[i] = v;
    }
}

__global__ void scatter_kernel(const int* __restrict__ rows) {
    int e = blockIdx.x * blockDim.x + threadIdx.x;
    if (e >= EE) return;
    int pos = atomicAdd(&g_cursor[rows[e]], 1);
    g_perm[pos] = e;
}

// Warp-per-row sort of edge ids (deterministic accumulation order).
// deg <= 32: in-register bitonic via shfl. deg > 32 (rare): lane-0 insertion sort.
__global__ void warpsort_kernel() {
    int gid = blockIdx.x * blockDim.x + threadIdx.x;
    int r = gid >> 5;
    int lane = threadIdx.x & 31;
    if (r >= NN) return;
    int s = g_rowptr[r], e = g_rowptr[r + 1];
    int deg = e - s;
    if (deg <= 1) return;
    if (deg <= 32) {
        int v = (lane < deg) ? g_perm[s + lane] : 0x7fffffff;
#pragma unroll
        for (int k = 2; k <= 32; k <<= 1) {
#pragma unroll
            for (int j = k >> 1; j > 0; j >>= 1) {
                int o = __shfl_xor_sync(0xffffffffu, v, j);
                bool dir = ((lane & k) == 0);
                bool lower = ((lane & j) == 0);
                int mn = min(v, o), mx = max(v, o);
                v = (dir == lower) ? mn : mx;
            }
        }
        if (lane < deg) g_perm[s + lane] = v;
    } else if (lane == 0) {
        for (int i = s + 1; i < e; i++) {
            int v = g_perm[i];
            int j = i - 1;
            while (j >= s && g_perm[j] > v) { g_perm[j + 1] = g_perm[j]; j--; }
            g_perm[j + 1] = v;
        }
    }
}

// ---------------- dropout masks + packed (col,val) per step ----------------
__global__ void keep_kernel(const int* __restrict__ cols, const float* __restrict__ adj,
                            uint32_t a0, uint32_t a1, uint32_t b0, uint32_t b1,
                            uint32_t c0, uint32_t c1) {
    int j = blockIdx.x * blockDim.x + threadIdx.x;
    if (j >= EE) return;
    int e = g_perm[j];
    float cb = __int_as_float(cols[e]);
    float v = adj[e];
    g_cv0[j] = make_float2(cb, v);
    v *= floorf(u01(rbits32(a0, a1, (uint32_t)e)) + 0.5f);
    g_cv1[j] = make_float2(cb, v);
    v *= floorf(u01(rbits32(b0, b1, (uint32_t)e)) + 0.25f);
    g_cv2[j] = make_float2(cb, v);
    v *= floorf(u01(rbits32(c0, c1, (uint32_t)e)) + 0.125f);
    g_cv3[j] = make_float2(cb, v);
}

// ---------------- fused propagation step: warp per row, lane = dim ----------------
template <int STEP>
__global__ void step_kernel(const float* __restrict__ embeds) {
    int gid = blockIdx.x * blockDim.x + threadIdx.x;
    int r = gid >> 5;
    int lane = threadIdx.x & 31;
    if (r >= NN) return;

    const float2* __restrict__ cv =
        (STEP == 0) ? g_cv0 : (STEP == 1) ? g_cv1 : (STEP == 2) ? g_cv2 : g_cv3;
    const float* __restrict__ emb_cur = (STEP == 0) ? embeds : ((STEP & 1) ? g_emb_a : g_emb_b);
    float*       emb_next = (STEP & 1) ? g_emb_b : g_emb_a;
    const float* num_cur = (STEP & 1) ? g_num_a : g_num_b;
    float*       num_next = (STEP & 1) ? g_num_b : g_num_a;

    int s = g_rowptr[r], e = g_rowptr[r + 1];
    float acc = 0.f, accn = 0.f, acco = 0.f;
#pragma unroll 4
    for (int j = s; j < e; j++) {
        float2 c2 = __ldg(&cv[j]);
        int c = __float_as_int(c2.x);
        float v = c2.y;
        acc += v * __ldg(&emb_cur[c * DD + lane]);
        if (STEP) accn += v * __ldg(&num_cur[c]);
        acco += v;
    }
    float ec = emb_cur[r * DD + lane];
    if (STEP == 0) {
        float en = acc - ec;
        emb_next[r * DD + lane] = en;
        g_emb_sum[r * DD + lane] = en;
        if (lane == 0) { num_next[r] = acco; g_num_sum[r] = acco; g_order[r] = acco; }
    } else {
        float od = g_order[r];
        float en = acc - ec - od * ec;
        emb_next[r * DD + lane] = en;
        g_emb_sum[r * DD + lane] += en;
        if (lane == 0) {
            float nn = accn - num_cur[r] - od;
            num_next[r] = nn;
            g_num_sum[r] += nn;
            g_order[r] = acco;
        }
    }
}

// ---------------- scoring (normalize + dot + Gumbel) with fused histogram ----------------
__global__ void score_kernel(const float* __restrict__ embeds, float* __restrict__ out,
                             int n_score_out) {
    int gid = blockIdx.x * blockDim.x + threadIdx.x;
    int i = gid >> 5;
    int lane = threadIdx.x & 31;
    if (i >= NN) return;

    float ns = g_num_sum[i] + 1e-8f;
    float sub = g_emb_sum[i * DD + lane] / ns;
    float em = embeds[i * DD + lane];
    float ss = sub * sub, ee = em * em;
    for (int o = 16; o; o >>= 1) {
        ss += __shfl_xor_sync(0xffffffffu, ss, o);
        ee += __shfl_xor_sync(0xffffffffu, ee, o);
    }
    float a = sub / fmaxf(sqrtf(ss), 1e-12f);
    float b = em / fmaxf(sqrtf(ee), 1e-12f);
    float d = a * b;
    for (int o = 16; o; o >>= 1) d += __shfl_xor_sync(0xffffffffu, d, o);

    if (lane == 0) {
        float u = u01(rbits32(0u, 7u, (uint32_t)i));   // key(7)
        float sc = d + (-logf(-logf(u)));
        g_scores[i] = sc;
        if (i < n_score_out) out[i] = sc;
        atomicAdd(&g_hist[score_key(sc) >> (32 - HBITS)], 1);
    }
}

// ---------------- top-k: threshold + compact + bitonic ----------------
__global__ void thresh_kernel() {   // 1 block, 1024 threads
    __shared__ int part[1024];
    const int T = 1024, CH = HSIZE / 1024;   // 128
    int t = threadIdx.x;
    int s = t * CH;
    int sum = 0;
    for (int i = 0; i < CH; i++) sum += g_hist[s + i];
    part[t] = sum;
    __syncthreads();
    if (t == 0) {
        int cum = 0, d = 0;
        for (int tt = T - 1; tt >= 0; tt--) {
            if (cum + part[tt] >= KTOP) {
                for (int b = tt * CH + CH - 1; b >= tt * CH; b--) {
                    int h = g_hist[b];
                    if (cum + h >= KTOP) { d = b; break; }
                    cum += h;
                }
                break;
            }
            cum += part[tt];
        }
        g_sel_digit = d;
    }
}

__global__ void compact_kernel() {
    int i = blockIdx.x * blockDim.x + threadIdx.x;
    if (i >= NN) return;
    uint32_t k = score_key(g_scores[i]);
    if ((int)(k >> (32 - HBITS)) >= g_sel_digit) {
        int p = atomicAdd(&g_cand_cnt, 1);
        if (p < CAP) { g_cand_key[p] = k; g_cand_idx[p] = i; }
    }
}

__global__ void final_kernel(float* __restrict__ out, int out_size) {  // 1 block, 1024 thr
    __shared__ unsigned long long sm[CAP];
    int n = g_cand_cnt; if (n > CAP) n = CAP;
    int m = KTOP; while (m < n) m <<= 1;      // power-of-2 sort size (usually 2048)
    for (int i = threadIdx.x; i < m; i += blockDim.x) {
        sm[i] = (i < n)
            ? ((((unsigned long long)g_cand_key[i]) << 32) | (uint32_t)(~(uint32_t)g_cand_idx[i]))
            : 0ull;
    }
    __syncthreads();
    for (int size = 2; size <= m; size <<= 1) {
        for (int stride = size >> 1; stride > 0; stride >>= 1) {
            for (int i = threadIdx.x; i < m / 2; i += blockDim.x) {
                int lo = 2 * i - (i & (stride - 1));
                int hi = lo + stride;
                bool desc = ((lo & size) == 0);
                unsigned long long a = sm[lo], b = sm[hi];
                bool sw = desc ? (a < b) : (a > b);
                if (sw) { sm[lo] = b; sm[hi] = a; }
            }
            __syncthreads();
        }
    }
    for (int j = threadIdx.x; j < KTOP; j += blockDim.x) {
        uint32_t idx = ~(uint32_t)(sm[j] & 0xffffffffull);
        if (out_size >= NN + KTOP) out[NN + j] = (float)idx;
        else if (out_size == KTOP) ((int*)out)[j] = (int)idx;
    }
}

// ---------------- launch ----------------
extern "C" void kernel_launch(void* const* d_in, const int* in_sizes, int n_in,
                              void* d_out, int out_size) {
    const int* rows = (const int*)d_in[0];       // edge_index[0]
    const int* cols = rows + EE;                 // edge_index[1]
    const float* adj = (const float*)d_in[1];
    const float* embeds = (const float*)d_in[2];
    float* out = (float*)d_out;
    (void)in_sizes; (void)n_in;

    // fold_in(key(42), i): threefry((0,42),(0,i)) -> derived key
    uint32_t fk[3][2];
    for (uint32_t i = 0; i < 3; i++) tf2x32(0u, 42u, 0u, i, fk[i][0], fk[i][1]);

    const int tb = 256;
    zero_kernel<<<(HSIZE + tb - 1) / tb, tb>>>();
    rowcnt_kernel<<<(EE + tb - 1) / tb, tb>>>(rows);
    scan1_kernel<<<SCAN_B, 1024>>>();
    scan2_kernel<<<1, 32>>>();
    scan3_kernel<<<SCAN_B, 1024>>>();
    scatter_kernel<<<(EE + tb - 1) / tb, tb>>>(rows);
    warpsort_kernel<<<(NN * 32 + tb - 1) / tb, tb>>>();
    keep_kernel<<<(EE + tb - 1) / tb, tb>>>(cols, adj,
        fk[0][0], fk[0][1], fk[1][0], fk[1][1], fk[2][0], fk[2][1]);

    step_kernel<0><<<(NN * 32 + tb - 1) / tb, tb>>>(embeds);
    step_kernel<1><<<(NN * 32 + tb - 1) / tb, tb>>>(embeds);
    step_kernel<2><<<(NN * 32 + tb - 1) / tb, tb>>>(embeds);
    step_kernel<3><<<(NN * 32 + tb - 1) / tb, tb>>>(embeds);

    int n_score_out = (out_size == KTOP) ? 0 : ((out_size < NN) ? out_size : NN);
    score_kernel<<<(NN * 32 + tb - 1) / tb, tb>>>(embeds, out, n_score_out);

    thresh_kernel<<<1, 1024>>>();
    compact_kernel<<<(NN + tb - 1) / tb, tb>>>();
    final_kernel<<<1, 1024>>>(out, out_size);
}